// round 4
// baseline (speedup 1.0000x reference)
#include <cuda_runtime.h>
#include <cstdint>

#define BB 4
#define SS 1024
#define HH 32
#define DD 8
#define EE 256
constexpr int NROWS = BB * SS * HH;   // 131072 quantum rows

// Scratch (allocation-free rule: __device__ globals)
__device__ float g_qh[BB * HH * SS * DD];   // [B,H,S,D] head-major, 4 MB
__device__ float g_att[BB * SS * EE];       // [B,S,E] attention out, 4 MB

// ---------- packed f32x2 helpers (Blackwell dual FP32 datapath) ----------
__device__ __forceinline__ unsigned long long pack2(float lo, float hi) {
    unsigned long long r;
    asm("mov.b64 %0, {%1, %2};" : "=l"(r) : "f"(lo), "f"(hi));
    return r;
}
__device__ __forceinline__ void unpack2(unsigned long long v, float& lo, float& hi) {
    asm("mov.b64 {%0, %1}, %2;" : "=f"(lo), "=f"(hi) : "l"(v));
}
__device__ __forceinline__ unsigned long long ffma2(unsigned long long a,
                                                    unsigned long long b,
                                                    unsigned long long c) {
    unsigned long long d;
    asm("fma.rn.f32x2 %0, %1, %2, %3;" : "=l"(d) : "l"(a), "l"(b), "l"(c));
    return d;
}
__device__ __forceinline__ unsigned long long fadd2(unsigned long long a,
                                                    unsigned long long b) {
    unsigned long long d;
    asm("add.rn.f32x2 %0, %1, %2;" : "=l"(d) : "l"(a), "l"(b));
    return d;
}
__device__ __forceinline__ float ex2(float x) {
    float y;
    asm("ex2.approx.ftz.f32 %0, %1;" : "=f"(y) : "f"(x));
    return y;
}

// ---------------------------------------------------------------------------
// Kernel 1: quantum heads via closed form.
// <Z_w> = prod_{j=0..w} cos(a_j) (w>=1), <Z_0> = prod_{j=1..7} cos(a_j).
// ---------------------------------------------------------------------------
__global__ void qheads_kernel(const float* __restrict__ x,
                              const float* __restrict__ theta) {
    int n = blockIdx.x * blockDim.x + threadIdx.x;
    if (n >= NROWS) return;

    float4 xa = *reinterpret_cast<const float4*>(x + (size_t)n * DD);
    float4 xb = *reinterpret_cast<const float4*>(x + (size_t)n * DD + 4);

    float c[8];
    c[0] = cosf(xa.x + theta[0]);
    c[1] = cosf(xa.y + theta[1]);
    c[2] = cosf(xa.z + theta[2]);
    c[3] = cosf(xa.w + theta[3]);
    c[4] = cosf(xb.x + theta[4]);
    c[5] = cosf(xb.y + theta[5]);
    c[6] = cosf(xb.z + theta[6]);
    c[7] = cosf(xb.w + theta[7]);

    float z[8];
    float p = c[0];
#pragma unroll
    for (int w = 1; w < 8; w++) { p *= c[w]; z[w] = p; }
    float s = c[7];
#pragma unroll
    for (int w = 6; w >= 1; w--) s *= c[w];
    z[0] = s;

    int h  = n % HH;
    int bs = n / HH;
    int b  = bs / SS;
    int si = bs % SS;
    float* dst = g_qh + ((((size_t)b * HH + h) * SS + si) * DD);
    *reinterpret_cast<float4*>(dst)     = make_float4(z[0], z[1], z[2], z[3]);
    *reinterpret_cast<float4*>(dst + 4) = make_float4(z[4], z[5], z[6], z[7]);
}

// ---------------------------------------------------------------------------
// Kernel 2: attention, query-pair lanes + 4 queries/thread.
// Block = one head (256 threads, thread owns queries 4t..4t+3 as 2 f32x2
// pairs). Keys stored DUPLICATED in dynamic SMEM: word[j][d] = {K[j][d],
// K[j][d]} (64 KB) so the whole warp LDS-broadcasts key rows with zero
// per-key packing ops. One key read serves 4 query dots.
// |score| <= sqrt(8): single-pass softmax, no max subtraction.
// ---------------------------------------------------------------------------
__global__ void __launch_bounds__(256) attn_kernel() {
    extern __shared__ unsigned long long sKd[];   // 64 KB, word (j,d) = j*8+d
    float* sF = reinterpret_cast<float*>(sKd);

    int bh  = blockIdx.x;           // 0..127
    int tid = threadIdx.x;

    // Load head tile, write each value duplicated: sF[j*16 + 2d + {0,1}] = K[j][d]
    const float4* src = reinterpret_cast<const float4*>(g_qh + (size_t)bh * SS * DD);
    for (int j = tid; j < SS; j += 256) {
        float4 a = src[j * 2];
        float4 b = src[j * 2 + 1];
        float4* w = reinterpret_cast<float4*>(sF + j * 16);
        w[0] = make_float4(a.x, a.x, a.y, a.y);
        w[1] = make_float4(a.z, a.z, a.w, a.w);
        w[2] = make_float4(b.x, b.x, b.y, b.y);
        w[3] = make_float4(b.z, b.z, b.w, b.w);
    }
    __syncthreads();

    const float kS = 1.4426950408889634f / 2.8284271247461903f;  // log2(e)/sqrt(8)
    int q0 = tid * 4;   // this thread's first query row

    // q2[p][d] = {Q[q0+2p][d], Q[q0+2p+1][d]} * kS   (read the duplicated smem)
    unsigned long long q2[2][8];
#pragma unroll
    for (int p = 0; p < 2; p++)
#pragma unroll
        for (int d = 0; d < 8; d++) {
            float a = sF[(q0 + 2 * p) * 16 + 2 * d] * kS;
            float b = sF[(q0 + 2 * p + 1) * 16 + 2 * d] * kS;
            q2[p][d] = pack2(a, b);
        }

    unsigned long long o[2][8];
#pragma unroll
    for (int p = 0; p < 2; p++)
#pragma unroll
        for (int d = 0; d < 8; d++) o[p][d] = 0ULL;
    unsigned long long l2[2] = {0ULL, 0ULL};

    const ulonglong2* kp2 = reinterpret_cast<const ulonglong2*>(sKd);

#pragma unroll 2
    for (int j = 0; j < SS; j++) {
        // key row j, duplicated lanes: 4 x LDS128 broadcast
        ulonglong2 w01 = kp2[j * 4 + 0];
        ulonglong2 w23 = kp2[j * 4 + 1];
        ulonglong2 w45 = kp2[j * 4 + 2];
        ulonglong2 w67 = kp2[j * 4 + 3];

#pragma unroll
        for (int p = 0; p < 2; p++) {
            unsigned long long acc = ffma2(q2[p][0], w01.x, 0ULL);
            acc = ffma2(q2[p][1], w01.y, acc);
            acc = ffma2(q2[p][2], w23.x, acc);
            acc = ffma2(q2[p][3], w23.y, acc);
            acc = ffma2(q2[p][4], w45.x, acc);
            acc = ffma2(q2[p][5], w45.y, acc);
            acc = ffma2(q2[p][6], w67.x, acc);
            acc = ffma2(q2[p][7], w67.y, acc);

            float s0, s1;
            unpack2(acc, s0, s1);
            unsigned long long pp = pack2(ex2(s0), ex2(s1));   // {p_q(2p), p_q(2p+1)}

            l2[p] = fadd2(l2[p], pp);
            o[p][0] = ffma2(pp, w01.x, o[p][0]);
            o[p][1] = ffma2(pp, w01.y, o[p][1]);
            o[p][2] = ffma2(pp, w23.x, o[p][2]);
            o[p][3] = ffma2(pp, w23.y, o[p][3]);
            o[p][4] = ffma2(pp, w45.x, o[p][4]);
            o[p][5] = ffma2(pp, w45.y, o[p][5]);
            o[p][6] = ffma2(pp, w67.x, o[p][6]);
            o[p][7] = ffma2(pp, w67.y, o[p][7]);
        }
    }

    int b = bh >> 5, h = bh & 31;
#pragma unroll
    for (int p = 0; p < 2; p++) {
        float la, lb;
        unpack2(l2[p], la, lb);
        float inva = 1.f / la, invb = 1.f / lb;

        float ra[8], rb[8];
#pragma unroll
        for (int d = 0; d < 8; d++) {
            float lo, hi;
            unpack2(o[p][d], lo, hi);
            ra[d] = lo * inva;
            rb[d] = hi * invb;
        }
        float* da = g_att + ((size_t)(b * SS + q0 + 2 * p)) * EE + h * DD;
        float* db = da + EE;
        *reinterpret_cast<float4*>(da)     = make_float4(ra[0], ra[1], ra[2], ra[3]);
        *reinterpret_cast<float4*>(da + 4) = make_float4(ra[4], ra[5], ra[6], ra[7]);
        *reinterpret_cast<float4*>(db)     = make_float4(rb[0], rb[1], rb[2], rb[3]);
        *reinterpret_cast<float4*>(db + 4) = make_float4(rb[4], rb[5], rb[6], rb[7]);
    }
}

// ---------------------------------------------------------------------------
// Kernel 3: out = g_att @ W^T.  M=4096, N=256, K=256, fp32.
// 64x64 tile, 256 threads, 4x4 micro-tile, k packed into f32x2 FMAs,
// pad-17 rows (max 2-way LDS conflict).
// ---------------------------------------------------------------------------
__global__ void gemm_kernel(const float* __restrict__ W, float* __restrict__ out) {
    __shared__ float As[64][17];
    __shared__ float Bs[64][17];

    int tx = threadIdx.x, ty = threadIdx.y;
    int tid = ty * 16 + tx;
    int m0 = blockIdx.y * 64, n0 = blockIdx.x * 64;

    unsigned long long acc2[4][4];
#pragma unroll
    for (int i = 0; i < 4; i++)
#pragma unroll
        for (int j = 0; j < 4; j++) acc2[i][j] = 0ULL;

    int lr = tid >> 2;
    int lc = (tid & 3) * 4;

    for (int k0 = 0; k0 < EE; k0 += 16) {
        float4 av = *reinterpret_cast<const float4*>(
            &g_att[(size_t)(m0 + lr) * EE + k0 + lc]);
        float4 bv = *reinterpret_cast<const float4*>(
            &W[(size_t)(n0 + lr) * EE + k0 + lc]);
        As[lr][lc] = av.x; As[lr][lc + 1] = av.y;
        As[lr][lc + 2] = av.z; As[lr][lc + 3] = av.w;
        Bs[lr][lc] = bv.x; Bs[lr][lc + 1] = bv.y;
        Bs[lr][lc + 2] = bv.z; Bs[lr][lc + 3] = bv.w;
        __syncthreads();

#pragma unroll
        for (int kk = 0; kk < 16; kk += 2) {
            unsigned long long a[4], b[4];
#pragma unroll
            for (int i = 0; i < 4; i++) {
                float x0 = As[ty * 4 + i][kk], x1 = As[ty * 4 + i][kk + 1];
                a[i] = pack2(x0, x1);
            }
#pragma unroll
            for (int j = 0; j < 4; j++) {
                float x0 = Bs[tx * 4 + j][kk], x1 = Bs[tx * 4 + j][kk + 1];
                b[j] = pack2(x0, x1);
            }
#pragma unroll
            for (int i = 0; i < 4; i++)
#pragma unroll
                for (int j = 0; j < 4; j++)
                    acc2[i][j] = ffma2(a[i], b[j], acc2[i][j]);
        }
        __syncthreads();
    }

#pragma unroll
    for (int i = 0; i < 4; i++) {
        float v[4];
#pragma unroll
        for (int j = 0; j < 4; j++) {
            float lo, hi;
            unpack2(acc2[i][j], lo, hi);
            v[j] = lo + hi;
        }
        *reinterpret_cast<float4*>(&out[(size_t)(m0 + ty * 4 + i) * EE + n0 + tx * 4]) =
            make_float4(v[0], v[1], v[2], v[3]);
    }
}

// ---------------------------------------------------------------------------
constexpr int ATTN_SMEM = SS * 8 * 8;   // 65536 bytes

extern "C" void kernel_launch(void* const* d_in, const int* in_sizes, int n_in,
                              void* d_out, int out_size) {
    const float* x = nullptr;
    const float* theta = nullptr;
    const float* w = nullptr;
    for (int i = 0; i < n_in; i++) {
        if (in_sizes[i] == NROWS * DD)      x = (const float*)d_in[i];
        else if (in_sizes[i] == DD)         theta = (const float*)d_in[i];
        else if (in_sizes[i] == EE * EE)    w = (const float*)d_in[i];
    }

    // Host-side attribute set: not a stream op, graph-capture-safe,
    // deterministic (same call every time).
    cudaFuncSetAttribute(attn_kernel,
                         cudaFuncAttributeMaxDynamicSharedMemorySize, ATTN_SMEM);

    qheads_kernel<<<NROWS / 256, 256>>>(x, theta);
    attn_kernel<<<BB * HH, 256, ATTN_SMEM>>>();
    gemm_kernel<<<dim3(EE / 64, BB * SS / 64), dim3(16, 16)>>>(w, (float*)d_out);
}